// round 10
// baseline (speedup 1.0000x reference)
#include <cuda_runtime.h>
#include <cuda_bf16.h>

// Problem constants
#define TT   4096
#define HH   16
#define DKK  128
#define QKVC 6144
#define NELEM (TT * HH * DKK)   // 8388608

// Scratch (static __device__ globals — no runtime allocation)
// g_P packed per (t,h): [slot0(128) | a(128) | k(128) | slot384(128)]
// After prep: slot0 = ka_t, slot384 = q_t.
// pass2 overwrites in place (warp-private slots, safe):
//   slot0   := w_t  = ka_t ∘ a_{t-1} ∘ a_{t-2}
//   slot384 := q~_t = q_t ∘ a_t ∘ a_{t-1} ∘ a_{t-2}
__device__ __align__(16) float g_P [TT * HH * 512];
__device__ __align__(16) float g_BV[NELEM];        // b * (conv+silu v)
__device__ __align__(16) float g_S8[TT * HH * 8];  // {b,R,Q,0, c0,c1,c2,0}
__device__ float g_B[TT * HH];                     // sigmoid(beta)

typedef unsigned long long ull;

// --------------------------------------------------------------------------
// f32x2 packed-math helpers (FFMA2 path; ptxas only emits via PTX f32x2)
// --------------------------------------------------------------------------
__device__ __forceinline__ ull ffma2(ull a, ull b, ull c) {
    ull d;
    asm("fma.rn.f32x2 %0, %1, %2, %3;" : "=l"(d) : "l"(a), "l"(b), "l"(c));
    return d;
}
__device__ __forceinline__ ull fmul2(ull a, ull b) {
    ull d;
    asm("mul.rn.f32x2 %0, %1, %2;" : "=l"(d) : "l"(a), "l"(b));
    return d;
}
__device__ __forceinline__ float hsum2(ull a) {
    float lo, hi;
    asm("mov.b64 {%0, %1}, %2;" : "=f"(lo), "=f"(hi) : "l"(a));
    return lo + hi;
}
__device__ __forceinline__ ull pack2(float x) {
    ull d;
    asm("mov.b64 %0, {%1, %1};" : "=l"(d) : "f"(x));
    return d;
}
__device__ __forceinline__ ull packAB(float a, float b) {
    ull d;
    asm("mov.b64 %0, {%1, %2};" : "=l"(d) : "f"(a), "f"(b));
    return d;
}
__device__ __forceinline__ void unpack2(float& lo, float& hi, ull a) {
    asm("mov.b64 {%0, %1}, %2;" : "=f"(lo), "=f"(hi) : "l"(a));
}

// cp.async helper
__device__ __forceinline__ void cp16(float* dst, const float* src) {
    unsigned d = (unsigned)__cvta_generic_to_shared(dst);
    asm volatile("cp.async.cg.shared.global [%0], [%1], 16;"
                 :: "r"(d), "l"(src) : "memory");
}

// --------------------------------------------------------------------------
// Kernel 1: conv1d(K=4, depthwise, causal) + SiLU + l2norm + gate precompute
// One warp per (t, h); lane handles 4 consecutive d via float4.
// --------------------------------------------------------------------------
__device__ __forceinline__ void conv_silu4(const float* __restrict__ x,
                                           const float* __restrict__ w,
                                           int t, int c, float out[4]) {
    float wz[4][4];
#pragma unroll
    for (int j = 0; j < 4; j++) {
        float4 wv = *(const float4*)(w + (size_t)(c + j) * 4);
        wz[j][0] = wv.x; wz[j][1] = wv.y; wz[j][2] = wv.z; wz[j][3] = wv.w;
    }
    float acc[4] = {0.f, 0.f, 0.f, 0.f};
#pragma unroll
    for (int tau = 0; tau < 4; tau++) {
        int tt = t - 3 + tau;
        if (tt >= 0) {
            float4 xv = *(const float4*)(x + (size_t)tt * QKVC + c);
            acc[0] = fmaf(xv.x, wz[0][tau], acc[0]);
            acc[1] = fmaf(xv.y, wz[1][tau], acc[1]);
            acc[2] = fmaf(xv.z, wz[2][tau], acc[2]);
            acc[3] = fmaf(xv.w, wz[3][tau], acc[3]);
        }
    }
#pragma unroll
    for (int j = 0; j < 4; j++)
        out[j] = acc[j] / (1.f + expf(-acc[j]));   // SiLU
}

__global__ void prep_kernel(const float* __restrict__ qkv,
                            const float* __restrict__ fg,
                            const float* __restrict__ beta,
                            const float* __restrict__ w,
                            const float* __restrict__ A_log,
                            const float* __restrict__ dt_bias) {
    int gw   = (blockIdx.x * blockDim.x + threadIdx.x) >> 5;
    int lane = threadIdx.x & 31;
    if (gw >= TT * HH) return;
    int t = gw >> 4;
    int h = gw & 15;
    int d = lane * 4;
    int cq = h * DKK + d;

    float qy[4], ky[4], vy[4];
    conv_silu4(qkv, w, t, cq,        qy);
    conv_silu4(qkv, w, t, cq + 2048, ky);
    conv_silu4(qkv, w, t, cq + 4096, vy);

    // l2norm sums
    float sq = 0.f, sk = 0.f;
#pragma unroll
    for (int j = 0; j < 4; j++) {
        sq = fmaf(qy[j], qy[j], sq);
        sk = fmaf(ky[j], ky[j], sk);
    }
#pragma unroll
    for (int m = 16; m > 0; m >>= 1) {
        sq += __shfl_xor_sync(0xffffffffu, sq, m);
        sk += __shfl_xor_sync(0xffffffffu, sk, m);
    }
    float se_q = sq + 1e-6f, se_k = sk + 1e-6f;
    float rq = rsqrtf(se_q); rq = rq * (1.5f - 0.5f * se_q * rq * rq);  // Newton
    float rk = rsqrtf(se_k); rk = rk * (1.5f - 0.5f * se_k * rk * rk);
    rq *= 0.08838834764831845f;   // DK^-0.5

    // gate
    float ea = expf(A_log[h]);
    float4 fgv = *(const float4*)(fg + (size_t)t * (HH * DKK) + h * DKK + d);
    float4 dbv = *(const float4*)(dt_bias + h * DKK + d);
    float zf[4] = {fgv.x + dbv.x, fgv.y + dbv.y, fgv.z + dbv.z, fgv.w + dbv.w};

    float bb = 1.f / (1.f + expf(-beta[t * HH + h]));

    float qn[4], kn[4], av[4], kav[4];
#pragma unroll
    for (int j = 0; j < 4; j++) {
        float z  = zf[j];
        float sp = (z > 20.f) ? z : log1pf(expf(z));   // softplus
        av[j]  = expf(-ea * sp);                       // a = exp(g)
        qn[j]  = qy[j] * rq;
        kn[j]  = ky[j] * rk;
        kav[j] = kn[j] * av[j];
    }

    size_t pb = ((size_t)t * HH + h) * 512 + d;
    *(float4*)(g_P + pb      ) = make_float4(kav[0], kav[1], kav[2], kav[3]);
    *(float4*)(g_P + pb + 128) = make_float4(av[0],  av[1],  av[2],  av[3]);
    *(float4*)(g_P + pb + 256) = make_float4(kn[0],  kn[1],  kn[2],  kn[3]);
    *(float4*)(g_P + pb + 384) = make_float4(qn[0],  qn[1],  qn[2],  qn[3]);
    *(float4*)(g_BV + ((size_t)t * HH + h) * DKK + d) =
        make_float4(vy[0] * bb, vy[1] * bb, vy[2] * bb, vy[3] * bb);
    if (lane == 0)
        g_B[t * HH + h] = bb;
}

// --------------------------------------------------------------------------
// Kernel 1b: lookahead precompute. One warp per (t,h).
// Vectors (in-place overwrite of warp-private slots):
//   w_t  = ka_t ∘ a_{t-1} ∘ a_{t-2}            (slot0)
//   q~_t = q_t ∘ a_t ∘ a_{t-1} ∘ a_{t-2}       (slot384)
// Scalars (g_S8): R = (ka_t∘a_{t-1})·k_{t-2},  Q = ka_t·k_{t-1},
//   c0 = q_t·k_t,  c1 = (q_t∘a_t)·k_{t-1},  c2 = (q_t∘a_t∘a_{t-1})·k_{t-2}
// Negative t indices: a := 1, k := 0.
// --------------------------------------------------------------------------
__global__ void pass2_kernel() {
    int gw   = (blockIdx.x * blockDim.x + threadIdx.x) >> 5;
    int lane = threadIdx.x & 31;
    if (gw >= TT * HH) return;
    int t = gw >> 4;
    int h = gw & 15;
    int d = lane * 4;

    size_t bt = ((size_t)t * HH + h) * 512;
    const size_t ts = (size_t)HH * 512;

    float4 ka = *(const float4*)(g_P + bt +       d);
    float4 at = *(const float4*)(g_P + bt + 128 + d);
    float4 kt = *(const float4*)(g_P + bt + 256 + d);
    float4 qt = *(const float4*)(g_P + bt + 384 + d);
    float4 a1 = make_float4(1.f, 1.f, 1.f, 1.f);
    float4 a2 = make_float4(1.f, 1.f, 1.f, 1.f);
    float4 k1 = make_float4(0.f, 0.f, 0.f, 0.f);
    float4 k2 = make_float4(0.f, 0.f, 0.f, 0.f);
    if (t >= 1) {
        a1 = *(const float4*)(g_P + bt - ts + 128 + d);
        k1 = *(const float4*)(g_P + bt - ts + 256 + d);
    }
    if (t >= 2) {
        a2 = *(const float4*)(g_P + bt - 2 * ts + 128 + d);
        k2 = *(const float4*)(g_P + bt - 2 * ts + 256 + d);
    }
    float4 u   = make_float4(ka.x * a1.x, ka.y * a1.y, ka.z * a1.z, ka.w * a1.w);
    float4 wv  = make_float4(u.x * a2.x,  u.y * a2.y,  u.z * a2.z,  u.w * a2.w);
    float4 qa  = make_float4(qt.x * at.x, qt.y * at.y, qt.z * at.z, qt.w * at.w);
    float4 qaa = make_float4(qa.x * a1.x, qa.y * a1.y, qa.z * a1.z, qa.w * a1.w);
    float4 qtl = make_float4(qaa.x * a2.x, qaa.y * a2.y, qaa.z * a2.z, qaa.w * a2.w);

    float rp = fmaf(u.x,   k2.x, u.y   * k2.y) + fmaf(u.z,   k2.z, u.w   * k2.w);
    float qp = fmaf(ka.x,  k1.x, ka.y  * k1.y) + fmaf(ka.z,  k1.z, ka.w  * k1.w);
    float c0 = fmaf(qt.x,  kt.x, qt.y  * kt.y) + fmaf(qt.z,  kt.z, qt.w  * kt.w);
    float c1 = fmaf(qa.x,  k1.x, qa.y  * k1.y) + fmaf(qa.z,  k1.z, qa.w  * k1.w);
    float c2 = fmaf(qaa.x, k2.x, qaa.y * k2.y) + fmaf(qaa.z, k2.z, qaa.w * k2.w);
#pragma unroll
    for (int m = 16; m > 0; m >>= 1) {
        rp += __shfl_xor_sync(0xffffffffu, rp, m);
        qp += __shfl_xor_sync(0xffffffffu, qp, m);
        c0 += __shfl_xor_sync(0xffffffffu, c0, m);
        c1 += __shfl_xor_sync(0xffffffffu, c1, m);
        c2 += __shfl_xor_sync(0xffffffffu, c2, m);
    }

    *(float4*)(g_P + bt +       d) = wv;    // slot0   := w   (warp-private)
    *(float4*)(g_P + bt + 384 + d) = qtl;   // slot384 := q~  (warp-private)
    if (lane == 0) {
        size_t sb = ((size_t)t * HH + h) * 8;
        *(float4*)(g_S8 + sb)     = make_float4(g_B[t * HH + h], rp, qp, 0.f);
        *(float4*)(g_S8 + sb + 4) = make_float4(c0, c1, c2, 0.f);
    }
}

// --------------------------------------------------------------------------
// Kernel 2: gated delta-rule recurrence, fully deferred (3-step lookahead
// for BOTH the pred dot and the output dot).
// CTA = 256 threads (8 warps) = 16 v-columns; one warp = 2 v-columns.
// Lane owns k-quad 4*lane..4*lane+3 (distinct-per-lane LDS.128).
// State SA/SB = S[ki][colA/colB] as f32x2 pairs.
//
// Critical chain per step: 3 dependent packed FFMA2s:
//   r_t = P_t + d2*R_t + d1*Q_t;  dt = bv_t - b_t*r_t
// Output (short, off-chain): o_t = O~_t + d2*c2 + d1*c1 + dt*c0
// P_{t+3} = w_{t+3}.S_t and O~_{t+3} = q~_{t+3}.S_t reduced by interleaved
// butterfly shuffles with 3 steps of slack — latency never exposed.
// --------------------------------------------------------------------------
#define STGF 544   // floats per stage: 512 packed + 16 bv + 8 scalars + pad
#define NST  16    // 4 groups x 4 steps in-flight ring

__global__ void __launch_bounds__(256, 1)
recur_kernel(float* __restrict__ out) {
    __shared__ __align__(16) float sm[NST * STGF];

    const int tid  = threadIdx.x;
    const int warp = tid >> 5;
    const int lane = tid & 31;
    const int h    = blockIdx.x >> 3;
    const int vb   = (blockIdx.x & 7) * 16;       // CTA's 16-column slab
    float* outp = out + h * DKK + vb + warp * 2;  // float2 per (t, warp)

    auto issue = [&](int g) {
#pragma unroll
        for (int s = 0; s < 4; s++) {
            int tu = 4 * g + s;
            float* sp = sm + (tu & 15) * STGF;
            int t = (tu > TT - 1) ? (TT - 1) : tu;
            const float* gp = g_P + ((size_t)t * HH + h) * 512;
            if (tid < 128) cp16(sp + tid * 4, gp + tid * 4);
            if (tid >= 128 && tid < 132)
                cp16(sp + 512 + (tid - 128) * 4,
                     g_BV + ((size_t)t * HH + h) * DKK + vb + (tid - 128) * 4);
            if (tid == 132 || tid == 133)
                cp16(sp + 528 + (tid - 132) * 4,
                     g_S8 + ((size_t)t * HH + h) * 8 + (tid - 132) * 4);
        }
        asm volatile("cp.async.commit_group;" ::: "memory");
    };

    issue(0); issue(1); issue(2);

    ull SA0 = 0, SA1 = 0, SB0 = 0, SB1 = 0;
    ull Pq[4] = {0, 0, 0, 0};     // packed reduced P for steps t..t+3
    ull Oq[4] = {0, 0, 0, 0};     // packed reduced O~ for steps t..t+3
    ull d1 = 0, d2 = 0;           // packed delta_{t-1}, delta_{t-2}

    for (int g = 0; g < TT / 4; g++) {
        // groups g and g+1 complete (w,q~ of t+3 live in group g+1)
        asm volatile("cp.async.wait_group 1;" ::: "memory");
        __syncthreads();
#pragma unroll
        for (int s = 0; s < 4; s++) {
            const int t = 4 * g + s;
            const float* spb = sm + (t & 15) * STGF;
            const float* spn = sm + ((t + 3) & 15) * STGF;
            const int lo = lane * 4;

            // distinct-per-lane array loads (one LDS.128 per array)
            ulonglong2 A  = *(const ulonglong2*)(spb + 128 + lo);
            ulonglong2 K  = *(const ulonglong2*)(spb + 256 + lo);
            ulonglong2 W  = *(const ulonglong2*)(spn +       lo);  // w_{t+3}
            ulonglong2 Qt = *(const ulonglong2*)(spn + 384 + lo);  // q~_{t+3}

            float4 s4a = *(const float4*)(spb + 528);    // {b, R, Q, -}
            float4 s4b = *(const float4*)(spb + 532);    // {c0, c1, c2, -}
            ull R2  = pack2(s4a.y);
            ull Q2  = pack2(s4a.z);
            ull nB2 = pack2(-s4a.x);
            ull C0  = pack2(s4b.x);
            ull C1  = pack2(s4b.y);
            ull C2  = pack2(s4b.z);
            ull BV2 = *(const ull*)(spb + 512 + warp * 2);  // (colA,colB)

            // ---- critical chain: 3 dependent packed FFMA2s ----
            ull r  = ffma2(d2, R2, Pq[s]);
            r      = ffma2(d1, Q2, r);
            ull dt = ffma2(nB2, r, BV2);

            // ---- output: short off-chain tail ----
            ull o = ffma2(d2, C2, Oq[s]);
            o     = ffma2(d1, C1, o);
            o     = ffma2(dt, C0, o);
            d2 = d1; d1 = dt;
            if (lane == 0) {
                float xA, xB; unpack2(xA, xB, o);
                *(float2*)(outp + (size_t)t * (HH * DKK)) = make_float2(xA, xB);
            }

            // ---- off-chain: S update + deferred dots for step t+3 ----
            float dA, dB; unpack2(dA, dB, dt);
            ull DA = pack2(dA), DB = pack2(dB);
            SA0 = ffma2(A.x, SA0, fmul2(K.x, DA));
            SA1 = ffma2(A.y, SA1, fmul2(K.y, DA));
            SB0 = ffma2(A.x, SB0, fmul2(K.x, DB));
            SB1 = ffma2(A.y, SB1, fmul2(K.y, DB));

            float pA = hsum2(ffma2(W.x,  SA0, fmul2(W.y,  SA1)));
            float pB = hsum2(ffma2(W.x,  SB0, fmul2(W.y,  SB1)));
            float oA = hsum2(ffma2(Qt.x, SA0, fmul2(Qt.y, SA1)));
            float oB = hsum2(ffma2(Qt.x, SB0, fmul2(Qt.y, SB1)));
            // 5-level butterfly, four interleaved chains (all off-chain:
            // results consumed 3 steps later)
#pragma unroll
            for (int m = 1; m < 32; m <<= 1) {
                pA += __shfl_xor_sync(0xffffffffu, pA, m);
                pB += __shfl_xor_sync(0xffffffffu, pB, m);
                oA += __shfl_xor_sync(0xffffffffu, oA, m);
                oB += __shfl_xor_sync(0xffffffffu, oB, m);
            }
            Pq[(s + 3) & 3] = packAB(pA, pB);   // P_{t+3}  = w_{t+3} . S_t
            Oq[(s + 3) & 3] = packAB(oA, oB);   // O~_{t+3} = q~_{t+3} . S_t
        }
        issue(g + 3);
    }
}

// --------------------------------------------------------------------------
extern "C" void kernel_launch(void* const* d_in, const int* in_sizes, int n_in,
                              void* d_out, int out_size) {
    const float* mixed_qkv   = (const float*)d_in[0];
    const float* forget_gate = (const float*)d_in[1];
    const float* beta        = (const float*)d_in[2];
    const float* conv_w      = (const float*)d_in[3];
    const float* A_log       = (const float*)d_in[4];
    const float* dt_bias     = (const float*)d_in[5];
    float* out = (float*)d_out;

    prep_kernel<<<(TT * HH) / 8, 256>>>(mixed_qkv, forget_gate, beta,
                                        conv_w, A_log, dt_bias);
    pass2_kernel<<<(TT * HH) / 8, 256>>>();
    recur_kernel<<<128, 256>>>(out);
}